// round 10
// baseline (speedup 1.0000x reference)
#include <cuda_runtime.h>

#define SZ 256
#define NCH 8
#define NPIX (SZ*SZ)
#define WPR 8         // words per row

// Per-channel occupancy bitmasks: 8 channels x 256 rows x 8 words = 64KB
__device__ unsigned int g_maskbits[NCH * SZ * WPR];

__global__ void build_masks_kernel(const int* __restrict__ lookup) {
    int y = blockIdx.x;
    int x = threadIdx.x;
    int v = lookup[y * SZ + x];
    int w = x >> 5;
    #pragma unroll
    for (int c = 0; c < NCH; ++c) {
        unsigned int mk = __ballot_sync(0xFFFFFFFFu, v == c + 1);
        if ((x & 31) == 0)
            g_maskbits[(c * SZ + y) * WPR + w] = mk;
    }
}

// Process one unfilled pixel: exact 4-NN via seeded row scan + pruned
// continuation; rare exact ring-search fallback.
static __device__ __forceinline__ void process_pixel(
    const unsigned int* __restrict__ m, const float* __restrict__ img,
    float* __restrict__ out, int c, int y0, int x0)
{
    const int pix = (y0 << 8) + x0;

    // Filled pixel keeps its (masked) value
    if ((m[(y0 << 3) + (x0 >> 5)] >> (x0 & 31)) & 1u) {
        out[c * NPIX + pix] = __ldg(&img[pix]);
        return;
    }

    // Top-4 as 32-bit keys (d2<<16)|idx. In the scan phase d2 <= 58+... < 2^16.
    // Ascending key order == top_k order (smallest d2, ties -> smallest idx).
    unsigned int k0 = ~0u, k1 = ~0u, k2 = ~0u, k3 = ~0u;

    auto ins32 = [&](unsigned int key) {
        if (key < k3) {
            k3 = key;
            if (k3 < k2) {
                unsigned int t = k2; k2 = k3; k3 = t;
                if (k2 < k1) {
                    t = k1; k1 = k2; k2 = t;
                    if (k1 < k0) { t = k0; k0 = k1; k1 = t; }
                }
            }
        }
    };

    // Scan bits x in [xlo,xhi] (width <= 32) of row yy via funnel shift.
    auto scan_row = [&](int yy, int xlo, int xhi) {
        if ((unsigned)yy >= SZ) return;
        xlo = xlo < 0 ? 0 : xlo;
        xhi = xhi > SZ - 1 ? SZ - 1 : xhi;
        const unsigned int* row = &m[yy << 3];
        const int wl = xlo >> 5;
        // row[wl+1] may touch the pad word; its bits are always masked out.
        unsigned int win = __funnelshift_r(row[wl], row[wl + 1], xlo);
        win &= 0xFFFFFFFFu >> (31 - (xhi - xlo));
        if (!win) return;
        const int dy = yy - y0;
        const unsigned int base =
            ((unsigned int)(dy * dy) << 16) + (unsigned int)((yy << 8) + xlo);
        const int off = xlo - x0;
        do {
            int b = __ffs(win) - 1;
            win &= win - 1;
            int dx = b + off;
            ins32(base + (unsigned int)b + ((unsigned int)(dx * dx) << 16));
        } while (win);
    };

    // ---- Seed: rows |dy|<=2, width |dx|<=7 ----
    #pragma unroll
    for (int dy = -2; dy <= 2; ++dy)
        scan_row(y0 + dy, x0 - 7, x0 + 7);

    // ---- Continuation: dy >= 3. Width 7 until 4 held; then inclusive
    // floor(sqrt(B - dy^2)) pruning (skipped cells have d2 > B, exact). ----
    for (int dy = 3; dy < SZ; ++dy) {
        int u = 7;
        if (k3 != ~0u) {
            unsigned int B = k3 >> 16;
            unsigned int dy2 = (unsigned int)(dy * dy);
            if (dy2 > B) break;
            int rem = (int)(B - dy2);
            u = __float2int_rd(sqrtf((float)rem));
            if ((u + 1) * (u + 1) <= rem) ++u;   // exact floor(sqrt(rem))
            if (u * u > rem) --u;
        }
        scan_row(y0 - dy, x0 - u, x0 + u);
        scan_row(y0 + dy, x0 - u, x0 + u);
    }

    unsigned int ridx[4], rd2[4];

    // Every skipped cell has |dx|>7 (d2 >= 64) or d2 > B >= final d2_4.
    // Exact iff final d2_4 < 64 (strict: ties cannot be lost).
    if (k3 != ~0u && (k3 >> 16) < 64u) {
        ridx[0] = k0 & 0xFFFFu; rd2[0] = k0 >> 16;
        ridx[1] = k1 & 0xFFFFu; rd2[1] = k1 >> 16;
        ridx[2] = k2 & 0xFFFFu; rd2[2] = k2 >> 16;
        ridx[3] = k3 & 0xFFFFu; rd2[3] = k3 >> 16;
    } else {
        // ---- Extremely rare exact fallback: expanding Chebyshev rings ----
        unsigned long long b0 = ~0ULL, b1 = ~0ULL, b2 = ~0ULL, b3 = ~0ULL;
        int found = 0;

        auto visit = [&](int yy, int xx) {
            if ((unsigned)yy >= SZ || (unsigned)xx >= SZ) return;
            unsigned int word = m[(yy << 3) + (xx >> 5)];
            if ((word >> (xx & 31)) & 1u) {
                int dy = yy - y0, dx = xx - x0;
                unsigned int d2 = (unsigned int)(dy * dy + dx * dx);
                unsigned long long key =
                    ((unsigned long long)d2 << 16) | (unsigned int)((yy << 8) + xx);
                ++found;
                if (key < b3) {
                    b3 = key;
                    if (b3 < b2) {
                        unsigned long long t = b2; b2 = b3; b3 = t;
                        if (b2 < b1) {
                            t = b1; b1 = b2; b2 = t;
                            if (b1 < b0) { t = b0; b0 = b1; b1 = t; }
                        }
                    }
                }
            }
        };

        for (int r = 1; r < SZ; ++r) {
            if (found >= 4 && (unsigned int)(r * r) > (unsigned int)(b3 >> 16)) break;
            int yt = y0 - r, yb = y0 + r;
            for (int xx = x0 - r; xx <= x0 + r; ++xx) { visit(yt, xx); visit(yb, xx); }
            int xl = x0 - r, xr = x0 + r;
            for (int yy = y0 - r + 1; yy <= y0 + r - 1; ++yy) { visit(yy, xl); visit(yy, xr); }
        }

        unsigned long long keys[4] = { b0, b1, b2, b3 };
        #pragma unroll
        for (int i = 0; i < 4; ++i) {
            ridx[i] = (unsigned int)(keys[i] & 0xFFFFu);
            rd2[i]  = (unsigned int)(keys[i] >> 16);
        }
    }

    // Weighted by distance (as in reference), in top_k order.
    float num = 0.0f, den = 0.0f;
    #pragma unroll
    for (int i = 0; i < 4; ++i) {
        float dist = sqrtf((float)rd2[i]) * (1.0f / 256.0f);  // == sqrt(d2/65536)
        num += __ldg(&img[ridx[i]]) * dist;
        den += dist;
    }
    out[c * NPIX + pix] = num / den;
}

__global__ __launch_bounds__(256, 8) void knn_fill_kernel(
    const float* __restrict__ img, float* __restrict__ out)
{
    const int c  = blockIdx.y;   // channel 0..7
    const int x0 = threadIdx.x;  // col

    // Channel bitmask (8KB) + 4 pad words for the wl=7 speculative read.
    __shared__ __align__(16) unsigned int m[SZ * WPR + 4];
    {
        const uint4* src = (const uint4*)&g_maskbits[c * SZ * WPR];
        uint4* dst = (uint4*)m;
        dst[threadIdx.x]       = src[threadIdx.x];
        dst[threadIdx.x + 256] = src[threadIdx.x + 256];
    }
    __syncthreads();

    // Two rows per thread block -> mask load amortized, single grid wave.
    #pragma unroll 1
    for (int half = 0; half < 2; ++half)
        process_pixel(m, img, out, c, blockIdx.x * 2 + half, x0);
}

extern "C" void kernel_launch(void* const* d_in, const int* in_sizes, int n_in,
                              void* d_out, int out_size) {
    const float* coded  = (const float*)d_in[0];   // [1,1,256,256]
    const int*   lookup = (const int*)d_in[1];     // [256,256]
    float* out = (float*)d_out;                    // [1,8,256,256]

    build_masks_kernel<<<SZ, SZ>>>(lookup);
    dim3 grid(SZ / 2, NCH);
    knn_fill_kernel<<<grid, SZ>>>(coded, out);
}

// round 12
// speedup vs baseline: 1.4229x; 1.4229x over previous
#include <cuda_runtime.h>

#define SZ 256
#define NCH 8
#define NPIX (SZ*SZ)
#define WPR 8         // words per row

// Per-channel occupancy bitmasks: 8 channels x 256 rows x 8 words = 64KB
__device__ unsigned int g_maskbits[NCH * SZ * WPR];

__global__ void build_masks_kernel(const int* __restrict__ lookup) {
    int y = blockIdx.x;
    int x = threadIdx.x;
    int v = lookup[y * SZ + x];
    int w = x >> 5;
    #pragma unroll
    for (int c = 0; c < NCH; ++c) {
        unsigned int mk = __ballot_sync(0xFFFFFFFFu, v == c + 1);
        if ((x & 31) == 0)
            g_maskbits[(c * SZ + y) * WPR + w] = mk;
    }
}

// Process one unfilled pixel: exact 4-NN via seeded row scan + pruned
// continuation; rare exact ring-search fallback.
static __device__ __forceinline__ void process_pixel(
    const unsigned int* __restrict__ m, const float* __restrict__ img,
    float* __restrict__ out, int c, int y0, int x0)
{
    const int pix = (y0 << 8) + x0;

    // Filled pixel keeps its (masked) value
    if ((m[(y0 << 3) + (x0 >> 5)] >> (x0 & 31)) & 1u) {
        out[c * NPIX + pix] = __ldg(&img[pix]);
        return;
    }

    // Top-4 as 32-bit keys (d2<<16)|idx; d2 < 2^16 throughout the scan phase.
    // Ascending key order == top_k order (smallest d2, ties -> smallest idx).
    unsigned int k0 = ~0u, k1 = ~0u, k2 = ~0u, k3 = ~0u;

    auto ins32 = [&](unsigned int key) {
        if (key < k3) {
            k3 = key;
            if (k3 < k2) {
                unsigned int t = k2; k2 = k3; k3 = t;
                if (k2 < k1) {
                    t = k1; k1 = k2; k2 = t;
                    if (k1 < k0) { t = k0; k0 = k1; k1 = t; }
                }
            }
        }
    };

    // Scan bits x in [xlo,xhi] (width <= 32; here always <= 15) of row yy
    // via a single funnel-shifted window.
    auto scan_row = [&](int yy, int xlo, int xhi) {
        if ((unsigned)yy >= SZ) return;
        xlo = xlo < 0 ? 0 : xlo;
        xhi = xhi > SZ - 1 ? SZ - 1 : xhi;
        const unsigned int* row = &m[yy << 3];
        const int wl = xlo >> 5;
        // row[wl+1] may touch the pad word; those bits are always masked out.
        unsigned int win = __funnelshift_r(row[wl], row[wl + 1], xlo);
        win &= 0xFFFFFFFFu >> (31 - (xhi - xlo));
        if (!win) return;
        const int dy = yy - y0;
        const unsigned int base =
            ((unsigned int)(dy * dy) << 16) + (unsigned int)((yy << 8) + xlo);
        const int off = xlo - x0;
        do {
            int b = __ffs(win) - 1;
            win &= win - 1;
            int dx = b + off;
            ins32(base + (unsigned int)b + ((unsigned int)(dx * dx) << 16));
        } while (win);
    };

    // ---- Seed: rows |dy|<=2, width |dx|<=7 ----
    #pragma unroll
    for (int dy = -2; dy <= 2; ++dy)
        scan_row(y0 + dy, x0 - 7, x0 + 7);

    // ---- Continuation: dy >= 3. Width 7 until 4 held; then inclusive
    // floor(sqrt(B - dy^2)) pruning (skipped cells have d2 > B, exact). ----
    for (int dy = 3; dy < SZ; ++dy) {
        int u = 7;
        if (k3 != ~0u) {
            unsigned int B = k3 >> 16;
            unsigned int dy2 = (unsigned int)(dy * dy);
            if (dy2 > B) break;
            int rem = (int)(B - dy2);
            u = __float2int_rd(sqrtf((float)rem));
            if ((u + 1) * (u + 1) <= rem) ++u;   // exact floor(sqrt(rem))
            if (u * u > rem) --u;
        }
        scan_row(y0 - dy, x0 - u, x0 + u);
        scan_row(y0 + dy, x0 - u, x0 + u);
    }

    unsigned int ridx[4], rd2[4];

    // Every skipped cell has |dx|>7 (d2 >= 64) or d2 > B >= final d2_4.
    // Exact iff final d2_4 < 64 (strict: ties cannot be lost).
    if (k3 != ~0u && (k3 >> 16) < 64u) {
        ridx[0] = k0 & 0xFFFFu; rd2[0] = k0 >> 16;
        ridx[1] = k1 & 0xFFFFu; rd2[1] = k1 >> 16;
        ridx[2] = k2 & 0xFFFFu; rd2[2] = k2 >> 16;
        ridx[3] = k3 & 0xFFFFu; rd2[3] = k3 >> 16;
    } else {
        // ---- Extremely rare exact fallback: expanding Chebyshev rings ----
        unsigned long long b0 = ~0ULL, b1 = ~0ULL, b2 = ~0ULL, b3 = ~0ULL;
        int found = 0;

        auto visit = [&](int yy, int xx) {
            if ((unsigned)yy >= SZ || (unsigned)xx >= SZ) return;
            unsigned int word = m[(yy << 3) + (xx >> 5)];
            if ((word >> (xx & 31)) & 1u) {
                int dy = yy - y0, dx = xx - x0;
                unsigned int d2 = (unsigned int)(dy * dy + dx * dx);
                unsigned long long key =
                    ((unsigned long long)d2 << 16) | (unsigned int)((yy << 8) + xx);
                ++found;
                if (key < b3) {
                    b3 = key;
                    if (b3 < b2) {
                        unsigned long long t = b2; b2 = b3; b3 = t;
                        if (b2 < b1) {
                            t = b1; b1 = b2; b2 = t;
                            if (b1 < b0) { t = b0; b0 = b1; b1 = t; }
                        }
                    }
                }
            }
        };

        for (int r = 1; r < SZ; ++r) {
            if (found >= 4 && (unsigned int)(r * r) > (unsigned int)(b3 >> 16)) break;
            int yt = y0 - r, yb = y0 + r;
            for (int xx = x0 - r; xx <= x0 + r; ++xx) { visit(yt, xx); visit(yb, xx); }
            int xl = x0 - r, xr = x0 + r;
            for (int yy = y0 - r + 1; yy <= y0 + r - 1; ++yy) { visit(yy, xl); visit(yy, xr); }
        }

        unsigned long long keys[4] = { b0, b1, b2, b3 };
        #pragma unroll
        for (int i = 0; i < 4; ++i) {
            ridx[i] = (unsigned int)(keys[i] & 0xFFFFu);
            rd2[i]  = (unsigned int)(keys[i] >> 16);
        }
    }

    // Weighted by distance (as in reference), in top_k order.
    float num = 0.0f, den = 0.0f;
    #pragma unroll
    for (int i = 0; i < 4; ++i) {
        float dist = sqrtf((float)rd2[i]) * (1.0f / 256.0f);  // == sqrt(d2/65536)
        num += __ldg(&img[ridx[i]]) * dist;
        den += dist;
    }
    out[c * NPIX + pix] = num / den;
}

__global__ __launch_bounds__(512, 4) void knn_fill_kernel(
    const float* __restrict__ img, float* __restrict__ out)
{
    const int c   = blockIdx.y;          // channel 0..7
    const int tid = threadIdx.x;         // 0..511
    const int x0  = tid & 255;           // col
    const int sub = tid >> 8;            // which of the 2 rows

    // Channel bitmask (8KB) + 4 pad words for the wl=7 speculative read.
    __shared__ __align__(16) unsigned int m[SZ * WPR + 4];
    if (tid < 256) {
        const uint4* src = (const uint4*)&g_maskbits[c * SZ * WPR];
        uint4* dst = (uint4*)m;
        dst[tid]       = src[tid];
        dst[tid + 256] = src[tid + 256];
    }
    __syncthreads();

    // Two rows per block, processed by independent warps (no serialization).
    process_pixel(m, img, out, c, blockIdx.x * 2 + sub, x0);
}

extern "C" void kernel_launch(void* const* d_in, const int* in_sizes, int n_in,
                              void* d_out, int out_size) {
    const float* coded  = (const float*)d_in[0];   // [1,1,256,256]
    const int*   lookup = (const int*)d_in[1];     // [256,256]
    float* out = (float*)d_out;                    // [1,8,256,256]

    build_masks_kernel<<<SZ, SZ>>>(lookup);
    dim3 grid(SZ / 2, NCH);
    knn_fill_kernel<<<grid, 512>>>(coded, out);
}